// round 2
// baseline (speedup 1.0000x reference)
#include <cuda_runtime.h>
#include <math.h>

// Problem constants: B=1, S=4096, D=1024, H=16, DH=64
#define S_LEN   4096
#define D_MODEL 1024
#define NHEAD   16
#define DHEAD   64
#define QKV_LD  3072   // 3*D

// Scratch (device globals: allocation-free rule)
__device__ float g_qkv[S_LEN * QKV_LD];   // [s][3*D] : q at e=h*64+d, k at 1024+..., v at 2048+...
__device__ float g_ctx[S_LEN * D_MODEL];  // [s][h*64+d]

// ---------------------------------------------------------------------------
// C[M,N] = A[M,K] * B[N,K]^T + bias[N]   (both row-major, K contiguous)
// 128x128 block tile, K-tile 8, 256 threads, 8x8 register micro-tile.
// Next K-tile's global loads are issued before the current compute block so
// DRAM/L2 latency hides under the 512-FMA inner loop.
// ---------------------------------------------------------------------------
__global__ void __launch_bounds__(256) gemm_nt_bias(
    const float* __restrict__ A, const float* __restrict__ B,
    const float* __restrict__ bias, float* __restrict__ C,
    int M, int N, int K)
{
    __shared__ float As[8][128];
    __shared__ float Bs[8][128];

    const int tid = threadIdx.x;
    const int bm = blockIdx.y * 128;
    const int bn = blockIdx.x * 128;

    const int lr = tid >> 1;          // row within 128-tile for loads
    const int lk = (tid & 1) * 4;     // k offset (0 or 4)
    const int tx = tid & 15;
    const int ty = tid >> 4;
    const int m0 = ty * 8;
    const int n0 = tx * 8;

    float acc[8][8];
#pragma unroll
    for (int i = 0; i < 8; i++)
#pragma unroll
        for (int j = 0; j < 8; j++) acc[i][j] = 0.f;

    const float* Ap = A + (size_t)(bm + lr) * K + lk;
    const float* Bp = B + (size_t)(bn + lr) * K + lk;

    // Prologue: fetch first K-tile
    float4 av = *(const float4*)(Ap);
    float4 bv = *(const float4*)(Bp);

    for (int k0 = 0; k0 < K; k0 += 8) {
        __syncthreads();   // previous tile's compute done before overwrite
        As[lk + 0][lr] = av.x; As[lk + 1][lr] = av.y;
        As[lk + 2][lr] = av.z; As[lk + 3][lr] = av.w;
        Bs[lk + 0][lr] = bv.x; Bs[lk + 1][lr] = bv.y;
        Bs[lk + 2][lr] = bv.z; Bs[lk + 3][lr] = bv.w;
        __syncthreads();

        // Prefetch next tile; latency overlaps the FMA block below.
        if (k0 + 8 < K) {
            av = *(const float4*)(Ap + k0 + 8);
            bv = *(const float4*)(Bp + k0 + 8);
        }

#pragma unroll
        for (int k = 0; k < 8; k++) {
            float a[8], b[8];
#pragma unroll
            for (int i = 0; i < 8; i++) a[i] = As[k][m0 + i];
#pragma unroll
            for (int j = 0; j < 8; j++) b[j] = Bs[k][n0 + j];
#pragma unroll
            for (int i = 0; i < 8; i++)
#pragma unroll
                for (int j = 0; j < 8; j++)
                    acc[i][j] = fmaf(a[i], b[j], acc[i][j]);
        }
    }

#pragma unroll
    for (int i = 0; i < 8; i++) {
        float* cp = C + (size_t)(bm + m0 + i) * N + bn + n0;
#pragma unroll
        for (int j = 0; j < 8; j++) cp[j] = acc[i][j] + bias[bn + n0 + j];
    }
}

// ---------------------------------------------------------------------------
// Flash-style causal attention. One block = (64-row query tile, one head).
// 256 threads; 16x16 thread grid with 4x4 register micro-tiles for both
// the S = Q*K^T (64x64x64) and O += P*V (64x64x64) products.
// Online softmax; K and V share one SMEM buffer (K dead once S is in SMEM).
// ---------------------------------------------------------------------------
#define SPAD 65   // padded row stride to kill bank conflicts

__global__ void __launch_bounds__(256) attn_kernel(
    const float* __restrict__ qkv, float* __restrict__ ctx)
{
    extern __shared__ float sm[];
    float* Qs   = sm;                    // 64*65
    float* KVs  = sm + 64 * SPAD;        // 64*65
    float* Ss   = sm + 2 * 64 * SPAD;    // 64*65
    float* mst  = sm + 3 * 64 * SPAD;    // 64
    float* lst  = mst + 64;              // 64
    float* corr = lst + 64;              // 64

    const int tid = threadIdx.x;
    const int qi  = 63 - blockIdx.x;     // heavy tiles first
    const int h   = blockIdx.y;
    const int tx  = tid & 15;
    const int ty  = tid >> 4;
    const int m0  = ty * 4;
    const int n0  = tx * 4;
    const int hoff = h * DHEAD;

    // Load Q tile, pre-scaled by 1/sqrt(DH)
    for (int idx = tid; idx < 64 * 64; idx += 256) {
        int m = idx >> 6, d = idx & 63;
        Qs[m * SPAD + d] =
            qkv[(size_t)(qi * 64 + m) * QKV_LD + hoff + d] * 0.125f;
    }
    if (tid < 64) { mst[tid] = -1e30f; lst[tid] = 0.f; }

    float oacc[4][4];
#pragma unroll
    for (int i = 0; i < 4; i++)
#pragma unroll
        for (int j = 0; j < 4; j++) oacc[i][j] = 0.f;

    for (int jt = 0; jt <= qi; jt++) {
        __syncthreads();   // prev PV done / Q+state visible (first iter)
        // Load K tile
        for (int idx = tid; idx < 64 * 64; idx += 256) {
            int n = idx >> 6, d = idx & 63;
            KVs[n * SPAD + d] =
                qkv[(size_t)(jt * 64 + n) * QKV_LD + D_MODEL + hoff + d];
        }
        __syncthreads();

        // S = Q * K^T  (4x4 per thread)
        float sacc[4][4];
#pragma unroll
        for (int i = 0; i < 4; i++)
#pragma unroll
            for (int j = 0; j < 4; j++) sacc[i][j] = 0.f;
#pragma unroll 8
        for (int d = 0; d < 64; d++) {
            float a[4], b[4];
#pragma unroll
            for (int i = 0; i < 4; i++) a[i] = Qs[(m0 + i) * SPAD + d];
#pragma unroll
            for (int j = 0; j < 4; j++) b[j] = KVs[(n0 + j) * SPAD + d];
#pragma unroll
            for (int i = 0; i < 4; i++)
#pragma unroll
                for (int j = 0; j < 4; j++)
                    sacc[i][j] = fmaf(a[i], b[j], sacc[i][j]);
        }
        const bool diag = (jt == qi);
#pragma unroll
        for (int i = 0; i < 4; i++)
#pragma unroll
            for (int j = 0; j < 4; j++) {
                float v = sacc[i][j];
                if (diag && (n0 + j > m0 + i)) v = -1e30f;  // causal mask
                Ss[(m0 + i) * SPAD + n0 + j] = v;
            }
        __syncthreads();   // S complete -> KVs reusable, Ss readable

        // Load V tile into the (now dead) K buffer, overlapping softmax
        for (int idx = tid; idx < 64 * 64; idx += 256) {
            int n = idx >> 6, d = idx & 63;
            KVs[n * SPAD + d] =
                qkv[(size_t)(jt * 64 + n) * QKV_LD + 2 * D_MODEL + hoff + d];
        }

        // Online softmax: 4 threads per row, 16 contiguous cols each
        {
            const int row = tid >> 2;
            const int l4  = tid & 3;
            const int cb  = l4 * 16;
            float tmax = -1e30f;
#pragma unroll
            for (int c = 0; c < 16; c++)
                tmax = fmaxf(tmax, Ss[row * SPAD + cb + c]);
            tmax = fmaxf(tmax, __shfl_xor_sync(0xffffffffu, tmax, 1));
            tmax = fmaxf(tmax, __shfl_xor_sync(0xffffffffu, tmax, 2));
            const float mold = mst[row];
            const float mnew = fmaxf(mold, tmax);
            float lsum = 0.f;
#pragma unroll
            for (int c = 0; c < 16; c++) {
                float p = __expf(Ss[row * SPAD + cb + c] - mnew);
                Ss[row * SPAD + cb + c] = p;
                lsum += p;
            }
            lsum += __shfl_xor_sync(0xffffffffu, lsum, 1);
            lsum += __shfl_xor_sync(0xffffffffu, lsum, 2);
            if (l4 == 0) {
                const float cr = __expf(mold - mnew);
                mst[row]  = mnew;
                lst[row]  = lst[row] * cr + lsum;
                corr[row] = cr;
            }
        }
        __syncthreads();   // softmax state + V tile ready

        // Rescale O, then O += P * V
#pragma unroll
        for (int i = 0; i < 4; i++) {
            const float cr = corr[m0 + i];
#pragma unroll
            for (int j = 0; j < 4; j++) oacc[i][j] *= cr;
        }
#pragma unroll 8
        for (int k = 0; k < 64; k++) {
            float a[4], b[4];
#pragma unroll
            for (int i = 0; i < 4; i++) a[i] = Ss[(m0 + i) * SPAD + k];
#pragma unroll
            for (int j = 0; j < 4; j++) b[j] = KVs[k * SPAD + n0 + j];
#pragma unroll
            for (int i = 0; i < 4; i++)
#pragma unroll
                for (int j = 0; j < 4; j++)
                    oacc[i][j] = fmaf(a[i], b[j], oacc[i][j]);
        }
    }

    // Normalize and write context
#pragma unroll
    for (int i = 0; i < 4; i++) {
        const float inv = 1.f / lst[m0 + i];
        float* cp = ctx + (size_t)(qi * 64 + m0 + i) * D_MODEL + hoff + n0;
#pragma unroll
        for (int j = 0; j < 4; j++) cp[j] = oacc[i][j] * inv;
    }
}

// ---------------------------------------------------------------------------
extern "C" void kernel_launch(void* const* d_in, const int* in_sizes, int n_in,
                              void* d_out, int out_size)
{
    const float* x      = (const float*)d_in[0];  // [1,4096,1024]
    const float* Wqkv_w = (const float*)d_in[1];  // [3072,1024]
    const float* Wqkv_b = (const float*)d_in[2];  // [3072]
    const float* out_w  = (const float*)d_in[3];  // [1024,1024]
    const float* out_b  = (const float*)d_in[4];  // [1024]
    float* out = (float*)d_out;                    // [1,4096,1024]

    float *qkv, *ctx;
    cudaGetSymbolAddress((void**)&qkv, g_qkv);
    cudaGetSymbolAddress((void**)&ctx, g_ctx);

    const int attn_smem = (3 * 64 * SPAD + 3 * 64) * (int)sizeof(float); // 50688
    cudaFuncSetAttribute(attn_kernel,
                         cudaFuncAttributeMaxDynamicSharedMemorySize,
                         attn_smem);

    // 1) QKV projection: [4096,3072] = x[4096,1024] * Wqkv_w[3072,1024]^T + b
    gemm_nt_bias<<<dim3(QKV_LD / 128, S_LEN / 128), 256>>>(
        x, Wqkv_w, Wqkv_b, qkv, S_LEN, QKV_LD, D_MODEL);

    // 2) Causal flash attention per (query-tile, head)
    attn_kernel<<<dim3(S_LEN / 64, NHEAD), 256, attn_smem>>>(qkv, ctx);

    // 3) Output projection: [4096,1024] = ctx * out_w^T + out_b
    gemm_nt_bias<<<dim3(D_MODEL / 128, S_LEN / 128), 256>>>(
        ctx, out_w, out_b, out, S_LEN, D_MODEL, D_MODEL);
}

// round 6
// speedup vs baseline: 1.3697x; 1.3697x over previous
#include <cuda_runtime.h>
#include <cstdint>
#include <math.h>

// Problem constants: B=1, S=4096, D=1024, H=16, DH=64
#define S_LEN   4096
#define D_MODEL 1024
#define NHEAD   16
#define DHEAD   64
#define QKV_LD  3072   // 3*D

// Scratch (device globals: allocation-free rule)
__device__ float g_qkv [S_LEN * QKV_LD];
__device__ float g_ctx [S_LEN * D_MODEL];
__device__ float g_xr  [S_LEN * D_MODEL];
__device__ float g_wqkvr[QKV_LD * D_MODEL];
__device__ float g_outwr[D_MODEL * D_MODEL];

// ---------------------------------------------------------------------------
// Helpers
// ---------------------------------------------------------------------------
__device__ __forceinline__ uint32_t smem_u32(const void* p) {
    uint32_t a;
    asm("{ .reg .u64 t; cvta.to.shared.u64 t, %1; cvt.u32.u64 %0, t; }"
        : "=r"(a) : "l"(p));
    return a;
}
// tf32 cvt needs a b32 destination register
__device__ __forceinline__ float tf32_rn(float x) {
    uint32_t r;
    asm("cvt.rna.tf32.f32 %0, %1;" : "=r"(r) : "f"(x));
    return __uint_as_float(r);
}
__device__ __forceinline__ void cp_async16(uint32_t saddr, const void* g) {
    asm volatile("cp.async.cg.shared.global [%0], [%1], 16;"
                 :: "r"(saddr), "l"(g));
}
__device__ __forceinline__ void cp_commit() {
    asm volatile("cp.async.commit_group;" ::: "memory");
}
template <int N> __device__ __forceinline__ void cp_wait() {
    asm volatile("cp.async.wait_group %0;" :: "n"(N) : "memory");
}
// m16n8k8 tf32 mma (sm_80+ baseline PTX; valid on plain sm_100)
__device__ __forceinline__ void mma_tf32_16n8k8(
    float* c, const uint32_t* a, const uint32_t* b)
{
    asm volatile(
        "mma.sync.aligned.m16n8k8.row.col.f32.tf32.tf32.f32 "
        "{%0,%1,%2,%3}, {%4,%5,%6,%7}, {%8,%9}, {%0,%1,%2,%3};"
        : "+f"(c[0]), "+f"(c[1]), "+f"(c[2]), "+f"(c[3])
        : "r"(a[0]), "r"(a[1]), "r"(a[2]), "r"(a[3]), "r"(b[0]), "r"(b[1]));
}

// ---------------------------------------------------------------------------
// Elementwise tf32 rounding (RNA), float4 vectorized
// ---------------------------------------------------------------------------
__global__ void __launch_bounds__(256) round_tf32_kernel(
    const float4* __restrict__ in, float4* __restrict__ out, int n4)
{
    int i = blockIdx.x * blockDim.x + threadIdx.x;
    if (i < n4) {
        float4 v = in[i];
        v.x = tf32_rn(v.x); v.y = tf32_rn(v.y);
        v.z = tf32_rn(v.z); v.w = tf32_rn(v.w);
        out[i] = v;
    }
}

// ---------------------------------------------------------------------------
// tf32 mma.sync GEMM: C[M,N] = A[M,K] * B[N,K]^T + bias[N]
// 128x128 block, K-chunk 32, double-buffered cp.async.
// 8 warps in 2(m) x 4(n) grid; warp tile 64x32 = 4x4 m16n8k8 subtiles.
// SMEM tiles stored [row][k] padded to 36 floats/row (conflict-free frags).
// ---------------------------------------------------------------------------
#define ROWPAD      36
#define TILE_FLOATS (128 * ROWPAD)          // per matrix per stage
#define STAGE_FLOATS (2 * TILE_FLOATS)      // A + B
#define STAGE_BYTES  (STAGE_FLOATS * 4)     // 36864

__global__ void __launch_bounds__(256, 2)
gemm_tf32_mma(const float* __restrict__ A, const float* __restrict__ B,
              const float* __restrict__ bias, float* __restrict__ C,
              int M, int N, int K)
{
    extern __shared__ float smem[];
    const uint32_t sbase = smem_u32(smem);

    const int tid  = threadIdx.x;
    const int lane = tid & 31;
    const int wid  = tid >> 5;
    const int warp_m = wid >> 2;       // 0..1 -> 64 rows
    const int warp_n = wid & 3;        // 0..3 -> 32 cols
    const int g  = lane >> 2;          // groupid 0..7
    const int t  = lane & 3;           // thread-in-group 0..3

    const int bm = blockIdx.y * 128;
    const int bn = blockIdx.x * 128;
    const int NCH = K >> 5;            // K / 32

    float acc[4][4][4];
#pragma unroll
    for (int i = 0; i < 4; i++)
#pragma unroll
        for (int j = 0; j < 4; j++)
#pragma unroll
            for (int r = 0; r < 4; r++) acc[i][j][r] = 0.f;

    // chunk loader: 128 rows x 32 floats per matrix = 1024 x 16B chunks
    auto load_chunk = [&](int kc, int s) {
        const uint32_t sa = sbase + s * STAGE_BYTES;
        const float* ga = A + (size_t)bm * K + kc * 32;
        const float* gb = B + (size_t)bn * K + kc * 32;
#pragma unroll
        for (int j = 0; j < 4; j++) {
            int u = tid + 256 * j;       // 0..1023
            int row = u >> 3, c = u & 7;
            uint32_t off = (row * ROWPAD + c * 4) * 4;   // bytes
            cp_async16(sa + off,                   ga + (size_t)row * K + c * 4);
            cp_async16(sa + TILE_FLOATS * 4 + off, gb + (size_t)row * K + c * 4);
        }
        cp_commit();
    };

    auto compute = [&](int s) {
        const uint32_t* As = (const uint32_t*)(smem + s * STAGE_FLOATS);
        const uint32_t* Bs = As + TILE_FLOATS;
#pragma unroll
        for (int ks = 0; ks < 4; ks++) {
            const int k0 = ks * 8;
            uint32_t a[4][4], b[4][2];
#pragma unroll
            for (int mi = 0; mi < 4; mi++) {
                int row = warp_m * 64 + mi * 16;
                a[mi][0] = As[(row + g)     * ROWPAD + k0 + t];
                a[mi][1] = As[(row + g + 8) * ROWPAD + k0 + t];
                a[mi][2] = As[(row + g)     * ROWPAD + k0 + t + 4];
                a[mi][3] = As[(row + g + 8) * ROWPAD + k0 + t + 4];
            }
#pragma unroll
            for (int ni = 0; ni < 4; ni++) {
                int col = warp_n * 32 + ni * 8;
                b[ni][0] = Bs[(col + g) * ROWPAD + k0 + t];
                b[ni][1] = Bs[(col + g) * ROWPAD + k0 + t + 4];
            }
#pragma unroll
            for (int mi = 0; mi < 4; mi++)
#pragma unroll
                for (int ni = 0; ni < 4; ni++)
                    mma_tf32_16n8k8(acc[mi][ni], a[mi], b[ni]);
        }
    };

    load_chunk(0, 0);
    for (int kc = 0; kc < NCH; kc++) {
        const int s = kc & 1;
        if (kc + 1 < NCH) { load_chunk(kc + 1, s ^ 1); cp_wait<1>(); }
        else              { cp_wait<0>(); }
        __syncthreads();
        compute(s);
        __syncthreads();
    }

    // Epilogue: fragment layout -> C, add bias, float2 stores
#pragma unroll
    for (int mi = 0; mi < 4; mi++) {
        const int row0 = bm + warp_m * 64 + mi * 16 + g;
#pragma unroll
        for (int ni = 0; ni < 4; ni++) {
            const int col = bn + warp_n * 32 + ni * 8 + t * 2;
            const float bx = bias[col], by = bias[col + 1];
            float2 v0 = make_float2(acc[mi][ni][0] + bx, acc[mi][ni][1] + by);
            float2 v1 = make_float2(acc[mi][ni][2] + bx, acc[mi][ni][3] + by);
            *(float2*)(C + (size_t)row0 * N + col)       = v0;
            *(float2*)(C + (size_t)(row0 + 8) * N + col) = v1;
        }
    }
}

// ---------------------------------------------------------------------------
// Flash-style causal attention (round-2 passing version; ctx written
// tf32-rounded so the output projection needs no extra rounding pass).
// ---------------------------------------------------------------------------
#define SPAD 65

__global__ void __launch_bounds__(256) attn_kernel(
    const float* __restrict__ qkv, float* __restrict__ ctx)
{
    extern __shared__ float sm[];
    float* Qs   = sm;
    float* KVs  = sm + 64 * SPAD;
    float* Ss   = sm + 2 * 64 * SPAD;
    float* mst  = sm + 3 * 64 * SPAD;
    float* lst  = mst + 64;
    float* corr = lst + 64;

    const int tid = threadIdx.x;
    const int qi  = 63 - blockIdx.x;
    const int h   = blockIdx.y;
    const int tx  = tid & 15;
    const int ty  = tid >> 4;
    const int m0  = ty * 4;
    const int n0  = tx * 4;
    const int hoff = h * DHEAD;

    for (int idx = tid; idx < 64 * 64; idx += 256) {
        int m = idx >> 6, d = idx & 63;
        Qs[m * SPAD + d] =
            qkv[(size_t)(qi * 64 + m) * QKV_LD + hoff + d] * 0.125f;
    }
    if (tid < 64) { mst[tid] = -1e30f; lst[tid] = 0.f; }

    float oacc[4][4];
#pragma unroll
    for (int i = 0; i < 4; i++)
#pragma unroll
        for (int j = 0; j < 4; j++) oacc[i][j] = 0.f;

    for (int jt = 0; jt <= qi; jt++) {
        __syncthreads();
        for (int idx = tid; idx < 64 * 64; idx += 256) {
            int n = idx >> 6, d = idx & 63;
            KVs[n * SPAD + d] =
                qkv[(size_t)(jt * 64 + n) * QKV_LD + D_MODEL + hoff + d];
        }
        __syncthreads();

        float sacc[4][4];
#pragma unroll
        for (int i = 0; i < 4; i++)
#pragma unroll
            for (int j = 0; j < 4; j++) sacc[i][j] = 0.f;
#pragma unroll 8
        for (int d = 0; d < 64; d++) {
            float a[4], b[4];
#pragma unroll
            for (int i = 0; i < 4; i++) a[i] = Qs[(m0 + i) * SPAD + d];
#pragma unroll
            for (int j = 0; j < 4; j++) b[j] = KVs[(n0 + j) * SPAD + d];
#pragma unroll
            for (int i = 0; i < 4; i++)
#pragma unroll
                for (int j = 0; j < 4; j++)
                    sacc[i][j] = fmaf(a[i], b[j], sacc[i][j]);
        }
        const bool diag = (jt == qi);
#pragma unroll
        for (int i = 0; i < 4; i++)
#pragma unroll
            for (int j = 0; j < 4; j++) {
                float v = sacc[i][j];
                if (diag && (n0 + j > m0 + i)) v = -1e30f;
                Ss[(m0 + i) * SPAD + n0 + j] = v;
            }
        __syncthreads();

        for (int idx = tid; idx < 64 * 64; idx += 256) {
            int n = idx >> 6, d = idx & 63;
            KVs[n * SPAD + d] =
                qkv[(size_t)(jt * 64 + n) * QKV_LD + 2 * D_MODEL + hoff + d];
        }

        {
            const int row = tid >> 2;
            const int l4  = tid & 3;
            const int cb  = l4 * 16;
            float tmax = -1e30f;
#pragma unroll
            for (int c = 0; c < 16; c++)
                tmax = fmaxf(tmax, Ss[row * SPAD + cb + c]);
            tmax = fmaxf(tmax, __shfl_xor_sync(0xffffffffu, tmax, 1));
            tmax = fmaxf(tmax, __shfl_xor_sync(0xffffffffu, tmax, 2));
            const float mold = mst[row];
            const float mnew = fmaxf(mold, tmax);
            float lsum = 0.f;
#pragma unroll
            for (int c = 0; c < 16; c++) {
                float p = __expf(Ss[row * SPAD + cb + c] - mnew);
                Ss[row * SPAD + cb + c] = p;
                lsum += p;
            }
            lsum += __shfl_xor_sync(0xffffffffu, lsum, 1);
            lsum += __shfl_xor_sync(0xffffffffu, lsum, 2);
            if (l4 == 0) {
                const float cr = __expf(mold - mnew);
                mst[row]  = mnew;
                lst[row]  = lst[row] * cr + lsum;
                corr[row] = cr;
            }
        }
        __syncthreads();

#pragma unroll
        for (int i = 0; i < 4; i++) {
            const float cr = corr[m0 + i];
#pragma unroll
            for (int j = 0; j < 4; j++) oacc[i][j] *= cr;
        }
#pragma unroll 8
        for (int k = 0; k < 64; k++) {
            float a[4], b[4];
#pragma unroll
            for (int i = 0; i < 4; i++) a[i] = Ss[(m0 + i) * SPAD + k];
#pragma unroll
            for (int j = 0; j < 4; j++) b[j] = KVs[k * SPAD + n0 + j];
#pragma unroll
            for (int i = 0; i < 4; i++)
#pragma unroll
                for (int j = 0; j < 4; j++)
                    oacc[i][j] = fmaf(a[i], b[j], oacc[i][j]);
        }
    }

#pragma unroll
    for (int i = 0; i < 4; i++) {
        const float inv = 1.f / lst[m0 + i];
        float* cp = ctx + (size_t)(qi * 64 + m0 + i) * D_MODEL + hoff + n0;
#pragma unroll
        for (int j = 0; j < 4; j++) cp[j] = tf32_rn(oacc[i][j] * inv);
    }
}

// ---------------------------------------------------------------------------
extern "C" void kernel_launch(void* const* d_in, const int* in_sizes, int n_in,
                              void* d_out, int out_size)
{
    const float* x      = (const float*)d_in[0];
    const float* Wqkv_w = (const float*)d_in[1];
    const float* Wqkv_b = (const float*)d_in[2];
    const float* out_w  = (const float*)d_in[3];
    const float* out_b  = (const float*)d_in[4];
    float* out = (float*)d_out;

    float *qkv, *ctx, *xr, *wqkvr, *outwr;
    cudaGetSymbolAddress((void**)&qkv,   g_qkv);
    cudaGetSymbolAddress((void**)&ctx,   g_ctx);
    cudaGetSymbolAddress((void**)&xr,    g_xr);
    cudaGetSymbolAddress((void**)&wqkvr, g_wqkvr);
    cudaGetSymbolAddress((void**)&outwr, g_outwr);

    const int gemm_smem = 2 * STAGE_BYTES;   // 73728
    cudaFuncSetAttribute(gemm_tf32_mma,
                         cudaFuncAttributeMaxDynamicSharedMemorySize, gemm_smem);
    const int attn_smem = (3 * 64 * SPAD + 3 * 64) * (int)sizeof(float);
    cudaFuncSetAttribute(attn_kernel,
                         cudaFuncAttributeMaxDynamicSharedMemorySize, attn_smem);

    // 0) tf32-round tensor-core inputs (RNA, avoids truncation bias)
    {
        int n4 = S_LEN * D_MODEL / 4;
        round_tf32_kernel<<<(n4 + 255) / 256, 256>>>((const float4*)x,
                                                     (float4*)xr, n4);
        n4 = QKV_LD * D_MODEL / 4;
        round_tf32_kernel<<<(n4 + 255) / 256, 256>>>((const float4*)Wqkv_w,
                                                     (float4*)wqkvr, n4);
        n4 = D_MODEL * D_MODEL / 4;
        round_tf32_kernel<<<(n4 + 255) / 256, 256>>>((const float4*)out_w,
                                                     (float4*)outwr, n4);
    }

    // 1) QKV projection on tensor cores (mma.sync tf32)
    gemm_tf32_mma<<<dim3(QKV_LD / 128, S_LEN / 128), 256, gemm_smem>>>(
        xr, wqkvr, Wqkv_b, qkv, S_LEN, QKV_LD, D_MODEL);

    // 2) Causal flash attention
    attn_kernel<<<dim3(S_LEN / 64, NHEAD), 256, attn_smem>>>(qkv, ctx);

    // 3) Output projection on tensor cores
    gemm_tf32_mma<<<dim3(D_MODEL / 128, S_LEN / 128), 256, gemm_smem>>>(
        ctx, outwr, out_b, out, S_LEN, D_MODEL, D_MODEL);
}

// round 7
// speedup vs baseline: 2.9071x; 2.1224x over previous
#include <cuda_runtime.h>
#include <cstdint>
#include <math.h>

// Problem constants: B=1, S=4096, D=1024, H=16, DH=64
#define S_LEN   4096
#define D_MODEL 1024
#define NHEAD   16
#define DHEAD   64
#define QKV_LD  3072   // 3*D

// Scratch (device globals: allocation-free rule)
__device__ float g_qkv [S_LEN * QKV_LD];
__device__ float g_ctx [S_LEN * D_MODEL];
__device__ float g_xr  [S_LEN * D_MODEL];
__device__ float g_wqkvr[QKV_LD * D_MODEL];
__device__ float g_outwr[D_MODEL * D_MODEL];

// ---------------------------------------------------------------------------
// Helpers
// ---------------------------------------------------------------------------
__device__ __forceinline__ uint32_t smem_u32(const void* p) {
    uint32_t a;
    asm("{ .reg .u64 t; cvta.to.shared.u64 t, %1; cvt.u32.u64 %0, t; }"
        : "=r"(a) : "l"(p));
    return a;
}
__device__ __forceinline__ float tf32_rn(float x) {
    uint32_t r;
    asm("cvt.rna.tf32.f32 %0, %1;" : "=r"(r) : "f"(x));
    return __uint_as_float(r);
}
__device__ __forceinline__ void cp_async16(uint32_t saddr, const void* g) {
    asm volatile("cp.async.cg.shared.global [%0], [%1], 16;"
                 :: "r"(saddr), "l"(g));
}
__device__ __forceinline__ void cp_commit() {
    asm volatile("cp.async.commit_group;" ::: "memory");
}
template <int N> __device__ __forceinline__ void cp_wait() {
    asm volatile("cp.async.wait_group %0;" :: "n"(N) : "memory");
}
// m16n8k8 tf32 mma (sm_80+ baseline PTX)
__device__ __forceinline__ void mma_tf32_16n8k8(
    float* c, const uint32_t* a, const uint32_t* b)
{
    asm volatile(
        "mma.sync.aligned.m16n8k8.row.col.f32.tf32.tf32.f32 "
        "{%0,%1,%2,%3}, {%4,%5,%6,%7}, {%8,%9}, {%0,%1,%2,%3};"
        : "+f"(c[0]), "+f"(c[1]), "+f"(c[2]), "+f"(c[3])
        : "r"(a[0]), "r"(a[1]), "r"(a[2]), "r"(a[3]), "r"(b[0]), "r"(b[1]));
}

// ---------------------------------------------------------------------------
// Elementwise tf32 rounding (RNA), float4 vectorized
// ---------------------------------------------------------------------------
__global__ void __launch_bounds__(256) round_tf32_kernel(
    const float4* __restrict__ in, float4* __restrict__ out, int n4)
{
    int i = blockIdx.x * blockDim.x + threadIdx.x;
    if (i < n4) {
        float4 v = in[i];
        v.x = tf32_rn(v.x); v.y = tf32_rn(v.y);
        v.z = tf32_rn(v.z); v.w = tf32_rn(v.w);
        out[i] = v;
    }
}

// ---------------------------------------------------------------------------
// tf32 mma.sync GEMM: C[M,N] = A[M,K] * B[N,K]^T + bias[N]
// 128x128 block, K-chunk 32, double-buffered cp.async, 8 warps 2x4.
// round_out!=0 -> outputs tf32-rounded (feeds later tensor-core consumers).
// ---------------------------------------------------------------------------
#define ROWPAD      36
#define TILE_FLOATS (128 * ROWPAD)
#define STAGE_FLOATS (2 * TILE_FLOATS)
#define STAGE_BYTES  (STAGE_FLOATS * 4)

__global__ void __launch_bounds__(256, 2)
gemm_tf32_mma(const float* __restrict__ A, const float* __restrict__ B,
              const float* __restrict__ bias, float* __restrict__ C,
              int M, int N, int K, int round_out)
{
    extern __shared__ float smem[];
    const uint32_t sbase = smem_u32(smem);

    const int tid  = threadIdx.x;
    const int lane = tid & 31;
    const int wid  = tid >> 5;
    const int warp_m = wid >> 2;
    const int warp_n = wid & 3;
    const int g  = lane >> 2;
    const int t  = lane & 3;

    const int bm = blockIdx.y * 128;
    const int bn = blockIdx.x * 128;
    const int NCH = K >> 5;

    float acc[4][4][4];
#pragma unroll
    for (int i = 0; i < 4; i++)
#pragma unroll
        for (int j = 0; j < 4; j++)
#pragma unroll
            for (int r = 0; r < 4; r++) acc[i][j][r] = 0.f;

    auto load_chunk = [&](int kc, int s) {
        const uint32_t sa = sbase + s * STAGE_BYTES;
        const float* ga = A + (size_t)bm * K + kc * 32;
        const float* gb = B + (size_t)bn * K + kc * 32;
#pragma unroll
        for (int j = 0; j < 4; j++) {
            int u = tid + 256 * j;
            int row = u >> 3, c = u & 7;
            uint32_t off = (row * ROWPAD + c * 4) * 4;
            cp_async16(sa + off,                   ga + (size_t)row * K + c * 4);
            cp_async16(sa + TILE_FLOATS * 4 + off, gb + (size_t)row * K + c * 4);
        }
        cp_commit();
    };

    auto compute = [&](int s) {
        const uint32_t* As = (const uint32_t*)(smem + s * STAGE_FLOATS);
        const uint32_t* Bs = As + TILE_FLOATS;
#pragma unroll
        for (int ks = 0; ks < 4; ks++) {
            const int k0 = ks * 8;
            uint32_t a[4][4], b[4][2];
#pragma unroll
            for (int mi = 0; mi < 4; mi++) {
                int row = warp_m * 64 + mi * 16;
                a[mi][0] = As[(row + g)     * ROWPAD + k0 + t];
                a[mi][1] = As[(row + g + 8) * ROWPAD + k0 + t];
                a[mi][2] = As[(row + g)     * ROWPAD + k0 + t + 4];
                a[mi][3] = As[(row + g + 8) * ROWPAD + k0 + t + 4];
            }
#pragma unroll
            for (int ni = 0; ni < 4; ni++) {
                int col = warp_n * 32 + ni * 8;
                b[ni][0] = Bs[(col + g) * ROWPAD + k0 + t];
                b[ni][1] = Bs[(col + g) * ROWPAD + k0 + t + 4];
            }
#pragma unroll
            for (int mi = 0; mi < 4; mi++)
#pragma unroll
                for (int ni = 0; ni < 4; ni++)
                    mma_tf32_16n8k8(acc[mi][ni], a[mi], b[ni]);
        }
    };

    load_chunk(0, 0);
    for (int kc = 0; kc < NCH; kc++) {
        const int s = kc & 1;
        if (kc + 1 < NCH) { load_chunk(kc + 1, s ^ 1); cp_wait<1>(); }
        else              { cp_wait<0>(); }
        __syncthreads();
        compute(s);
        __syncthreads();
    }

#pragma unroll
    for (int mi = 0; mi < 4; mi++) {
        const int row0 = bm + warp_m * 64 + mi * 16 + g;
#pragma unroll
        for (int ni = 0; ni < 4; ni++) {
            const int col = bn + warp_n * 32 + ni * 8 + t * 2;
            const float bx = bias[col], by = bias[col + 1];
            float2 v0 = make_float2(acc[mi][ni][0] + bx, acc[mi][ni][1] + by);
            float2 v1 = make_float2(acc[mi][ni][2] + bx, acc[mi][ni][3] + by);
            if (round_out) {
                v0.x = tf32_rn(v0.x); v0.y = tf32_rn(v0.y);
                v1.x = tf32_rn(v1.x); v1.y = tf32_rn(v1.y);
            }
            *(float2*)(C + (size_t)row0 * N + col)       = v0;
            *(float2*)(C + (size_t)(row0 + 8) * N + col) = v1;
        }
    }
}

// ---------------------------------------------------------------------------
// Flash causal attention with tf32 mma.sync products.
// One block = (64-row query tile, head); 256 threads = 8 warps in 4(m)x2(n).
// S = Q*K^T and O += P*V both via m16n8k8. Online softmax in SMEM.
// qkv values are tf32-pre-rounded by the QKV GEMM epilogue.
// ---------------------------------------------------------------------------
#define APAD 68   // floats per SMEM row (bank stride 4 -> conflict-free frags)

__global__ void __launch_bounds__(256) attn_mma_kernel(
    const float* __restrict__ qkv, float* __restrict__ ctx)
{
    extern __shared__ float sm[];
    float* Qs   = sm;                    // 64*APAD
    float* KVs  = sm + 64 * APAD;        // 64*APAD (K, then V)
    float* Ss   = sm + 2 * 64 * APAD;    // 64*APAD (S -> P)
    float* mst  = sm + 3 * 64 * APAD;
    float* lst  = mst + 64;
    float* corr = lst + 64;

    const int tid  = threadIdx.x;
    const int lane = tid & 31;
    const int wid  = tid >> 5;
    const int wm = wid >> 1;            // 0..3 : 16-row warp tile
    const int wn = wid & 1;             // 0..1 : 32-col warp tile
    const int g  = lane >> 2;
    const int t  = lane & 3;
    const int qi = 63 - blockIdx.x;     // heavy tiles first
    const int h  = blockIdx.y;
    const int hoff = h * DHEAD;

    const uint32_t sQ  = smem_u32(Qs);
    const uint32_t sKV = smem_u32(KVs);
    const uint32_t* Qu = (const uint32_t*)Qs;
    const uint32_t* Ku = (const uint32_t*)KVs;
    const uint32_t* Su = (const uint32_t*)Ss;

    // async loads: 64 rows x 64 floats = 1024 x 16B chunks, 4 per thread
    auto load_tile = [&](uint32_t sdst, int tile, int sect) {
#pragma unroll
        for (int j = 0; j < 4; j++) {
            int u = tid + 256 * j;
            int row = u >> 4, c = u & 15;
            cp_async16(sdst + row * (APAD * 4) + c * 16,
                       qkv + (size_t)(tile * 64 + row) * QKV_LD + sect + hoff + c * 4);
        }
        cp_commit();
    };

    load_tile(sQ, qi, 0);           // Q
    load_tile(sKV, 0, D_MODEL);     // K tile 0

    if (tid < 64) { mst[tid] = -1e30f; lst[tid] = 0.f; }

    float oacc[4][4];
#pragma unroll
    for (int i = 0; i < 4; i++)
#pragma unroll
        for (int r = 0; r < 4; r++) oacc[i][r] = 0.f;

    const int r0 = wm * 16 + g;     // local rows owned by this thread
    const int r1 = r0 + 8;

    cp_wait<0>();
    __syncthreads();                // Q + K0 ready

    for (int jt = 0; jt <= qi; jt++) {
        // ---- S = Q * K^T (tf32 mma), scale folded after
        float sacc[4][4];
#pragma unroll
        for (int i = 0; i < 4; i++)
#pragma unroll
            for (int r = 0; r < 4; r++) sacc[i][r] = 0.f;
#pragma unroll
        for (int ks = 0; ks < 8; ks++) {
            const int k0 = ks * 8;
            uint32_t a[4], b[4][2];
            a[0] = Qu[r0 * APAD + k0 + t];
            a[1] = Qu[r1 * APAD + k0 + t];
            a[2] = Qu[r0 * APAD + k0 + t + 4];
            a[3] = Qu[r1 * APAD + k0 + t + 4];
#pragma unroll
            for (int ni = 0; ni < 4; ni++) {
                int col = wn * 32 + ni * 8;
                b[ni][0] = Ku[(col + g) * APAD + k0 + t];
                b[ni][1] = Ku[(col + g) * APAD + k0 + t + 4];
            }
#pragma unroll
            for (int ni = 0; ni < 4; ni++)
                mma_tf32_16n8k8(sacc[ni], a, b[ni]);
        }
        const bool diag = (jt == qi);
#pragma unroll
        for (int ni = 0; ni < 4; ni++) {
            const int col = wn * 32 + ni * 8 + t * 2;
            float v0 = sacc[ni][0] * 0.125f, v1 = sacc[ni][1] * 0.125f;
            float v2 = sacc[ni][2] * 0.125f, v3 = sacc[ni][3] * 0.125f;
            if (diag) {
                if (col     > r0) v0 = -1e30f;
                if (col + 1 > r0) v1 = -1e30f;
                if (col     > r1) v2 = -1e30f;
                if (col + 1 > r1) v3 = -1e30f;
            }
            *(float2*)(Ss + r0 * APAD + col) = make_float2(v0, v1);
            *(float2*)(Ss + r1 * APAD + col) = make_float2(v2, v3);
        }
        __syncthreads();            // S complete; KVs free

        // V tile load overlaps softmax
        load_tile(sKV, jt, 2 * D_MODEL);

        // ---- online softmax: 4 threads/row, 16 contiguous cols each
        {
            const int row = tid >> 2;
            const int l4  = tid & 3;
            const int cb  = l4 * 16;
            float tmax = -1e30f;
#pragma unroll
            for (int c = 0; c < 16; c++)
                tmax = fmaxf(tmax, Ss[row * APAD + cb + c]);
            tmax = fmaxf(tmax, __shfl_xor_sync(0xffffffffu, tmax, 1));
            tmax = fmaxf(tmax, __shfl_xor_sync(0xffffffffu, tmax, 2));
            const float mold = mst[row];
            const float mnew = fmaxf(mold, tmax);
            float lsum = 0.f;
#pragma unroll
            for (int c = 0; c < 16; c++) {
                float p = __expf(Ss[row * APAD + cb + c] - mnew);
                Ss[row * APAD + cb + c] = tf32_rn(p);
                lsum += p;
            }
            lsum += __shfl_xor_sync(0xffffffffu, lsum, 1);
            lsum += __shfl_xor_sync(0xffffffffu, lsum, 2);
            if (l4 == 0) {
                const float cr = __expf(mold - mnew);
                mst[row]  = mnew;
                lst[row]  = lst[row] * cr + lsum;
                corr[row] = cr;
            }
        }
        cp_wait<0>();
        __syncthreads();            // P + state + V ready

        // ---- rescale O, then O += P * V (tf32 mma)
        {
            const float cr0 = corr[r0], cr1 = corr[r1];
#pragma unroll
            for (int ni = 0; ni < 4; ni++) {
                oacc[ni][0] *= cr0; oacc[ni][1] *= cr0;
                oacc[ni][2] *= cr1; oacc[ni][3] *= cr1;
            }
        }
#pragma unroll
        for (int ks = 0; ks < 8; ks++) {
            const int k0 = ks * 8;
            uint32_t a[4], b[4][2];
            a[0] = Su[r0 * APAD + k0 + t];
            a[1] = Su[r1 * APAD + k0 + t];
            a[2] = Su[r0 * APAD + k0 + t + 4];
            a[3] = Su[r1 * APAD + k0 + t + 4];
#pragma unroll
            for (int ni = 0; ni < 4; ni++) {
                int col = wn * 32 + ni * 8;
                b[ni][0] = Ku[(k0 + t)     * APAD + col + g];   // V[n][d]
                b[ni][1] = Ku[(k0 + t + 4) * APAD + col + g];
            }
#pragma unroll
            for (int ni = 0; ni < 4; ni++)
                mma_tf32_16n8k8(oacc[ni], a, b[ni]);
        }
        __syncthreads();            // PV done; KVs free for next K

        if (jt < qi) {
            load_tile(sKV, jt + 1, D_MODEL);
            cp_wait<0>();
            __syncthreads();
        }
    }

    // ---- normalize and write context (tf32-rounded for the out-proj GEMM)
    {
        const float inv0 = 1.f / lst[r0];
        const float inv1 = 1.f / lst[r1];
#pragma unroll
        for (int ni = 0; ni < 4; ni++) {
            const int col = hoff + wn * 32 + ni * 8 + t * 2;
            float* c0 = ctx + (size_t)(qi * 64 + r0) * D_MODEL + col;
            float* c1 = ctx + (size_t)(qi * 64 + r1) * D_MODEL + col;
            c0[0] = tf32_rn(oacc[ni][0] * inv0);
            c0[1] = tf32_rn(oacc[ni][1] * inv0);
            c1[0] = tf32_rn(oacc[ni][2] * inv1);
            c1[1] = tf32_rn(oacc[ni][3] * inv1);
        }
    }
}

// ---------------------------------------------------------------------------
extern "C" void kernel_launch(void* const* d_in, const int* in_sizes, int n_in,
                              void* d_out, int out_size)
{
    const float* x      = (const float*)d_in[0];
    const float* Wqkv_w = (const float*)d_in[1];
    const float* Wqkv_b = (const float*)d_in[2];
    const float* out_w  = (const float*)d_in[3];
    const float* out_b  = (const float*)d_in[4];
    float* out = (float*)d_out;

    float *qkv, *ctx, *xr, *wqkvr, *outwr;
    cudaGetSymbolAddress((void**)&qkv,   g_qkv);
    cudaGetSymbolAddress((void**)&ctx,   g_ctx);
    cudaGetSymbolAddress((void**)&xr,    g_xr);
    cudaGetSymbolAddress((void**)&wqkvr, g_wqkvr);
    cudaGetSymbolAddress((void**)&outwr, g_outwr);

    const int gemm_smem = 2 * STAGE_BYTES;   // 73728
    cudaFuncSetAttribute(gemm_tf32_mma,
                         cudaFuncAttributeMaxDynamicSharedMemorySize, gemm_smem);
    const int attn_smem = (3 * 64 * APAD + 3 * 64) * (int)sizeof(float); // 52992
    cudaFuncSetAttribute(attn_mma_kernel,
                         cudaFuncAttributeMaxDynamicSharedMemorySize, attn_smem);

    // 0) tf32-round tensor-core inputs
    {
        int n4 = S_LEN * D_MODEL / 4;
        round_tf32_kernel<<<(n4 + 255) / 256, 256>>>((const float4*)x,
                                                     (float4*)xr, n4);
        n4 = QKV_LD * D_MODEL / 4;
        round_tf32_kernel<<<(n4 + 255) / 256, 256>>>((const float4*)Wqkv_w,
                                                     (float4*)wqkvr, n4);
        n4 = D_MODEL * D_MODEL / 4;
        round_tf32_kernel<<<(n4 + 255) / 256, 256>>>((const float4*)out_w,
                                                     (float4*)outwr, n4);
    }

    // 1) QKV projection (outputs tf32-rounded for the attention mma)
    gemm_tf32_mma<<<dim3(QKV_LD / 128, S_LEN / 128), 256, gemm_smem>>>(
        xr, wqkvr, Wqkv_b, qkv, S_LEN, QKV_LD, D_MODEL, 1);

    // 2) Causal flash attention on tensor cores
    attn_mma_kernel<<<dim3(S_LEN / 64, NHEAD), 256, attn_smem>>>(qkv, ctx);

    // 3) Output projection (fp32 outputs)
    gemm_tf32_mma<<<dim3(D_MODEL / 128, S_LEN / 128), 256, gemm_smem>>>(
        ctx, outwr, out_b, out, S_LEN, D_MODEL, D_MODEL, 0);
}

// round 9
// speedup vs baseline: 2.9153x; 1.0028x over previous
#include <cuda_runtime.h>
#include <cstdint>
#include <math.h>

// Problem constants: B=1, S=4096, D=1024, H=16, DH=64
#define S_LEN   4096
#define D_MODEL 1024
#define NHEAD   16
#define DHEAD   64
#define QKV_LD  3072   // 3*D

// Scratch (device globals: allocation-free rule)
__device__ float g_qkv [S_LEN * QKV_LD];
__device__ float g_ctx [S_LEN * D_MODEL];
__device__ float g_xr  [S_LEN * D_MODEL];
__device__ float g_wqkvr[QKV_LD * D_MODEL];
__device__ float g_outwr[D_MODEL * D_MODEL];

// ---------------------------------------------------------------------------
// Helpers
// ---------------------------------------------------------------------------
__device__ __forceinline__ uint32_t smem_u32(const void* p) {
    uint32_t a;
    asm("{ .reg .u64 t; cvta.to.shared.u64 t, %1; cvt.u32.u64 %0, t; }"
        : "=r"(a) : "l"(p));
    return a;
}
__device__ __forceinline__ float tf32_rn(float x) {
    uint32_t r;
    asm("cvt.rna.tf32.f32 %0, %1;" : "=r"(r) : "f"(x));
    return __uint_as_float(r);
}
__device__ __forceinline__ void cp_async16(uint32_t saddr, const void* g) {
    asm volatile("cp.async.cg.shared.global [%0], [%1], 16;"
                 :: "r"(saddr), "l"(g));
}
__device__ __forceinline__ void cp_commit() {
    asm volatile("cp.async.commit_group;" ::: "memory");
}
template <int N> __device__ __forceinline__ void cp_wait() {
    asm volatile("cp.async.wait_group %0;" :: "n"(N) : "memory");
}
// m16n8k8 tf32 mma (sm_80+ baseline PTX)
__device__ __forceinline__ void mma_tf32_16n8k8(
    float* c, const uint32_t* a, const uint32_t* b)
{
    asm volatile(
        "mma.sync.aligned.m16n8k8.row.col.f32.tf32.tf32.f32 "
        "{%0,%1,%2,%3}, {%4,%5,%6,%7}, {%8,%9}, {%0,%1,%2,%3};"
        : "+f"(c[0]), "+f"(c[1]), "+f"(c[2]), "+f"(c[3])
        : "r"(a[0]), "r"(a[1]), "r"(a[2]), "r"(a[3]), "r"(b[0]), "r"(b[1]));
}

// ---------------------------------------------------------------------------
// Elementwise tf32 rounding (RNA), float4 vectorized
// ---------------------------------------------------------------------------
__global__ void __launch_bounds__(256) round_tf32_kernel(
    const float4* __restrict__ in, float4* __restrict__ out, int n4)
{
    int i = blockIdx.x * blockDim.x + threadIdx.x;
    if (i < n4) {
        float4 v = in[i];
        v.x = tf32_rn(v.x); v.y = tf32_rn(v.y);
        v.z = tf32_rn(v.z); v.w = tf32_rn(v.w);
        out[i] = v;
    }
}

// ---------------------------------------------------------------------------
// tf32 mma.sync GEMM: C[M,N] = A[M,K] * B[N,K]^T + bias[N]
// 128x128 block, K-chunk 32, double-buffered cp.async, 8 warps 2x4.
// round_out!=0 -> outputs tf32-rounded (feeds later tensor-core consumers).
// ---------------------------------------------------------------------------
#define ROWPAD      36
#define TILE_FLOATS (128 * ROWPAD)
#define STAGE_FLOATS (2 * TILE_FLOATS)
#define STAGE_BYTES  (STAGE_FLOATS * 4)

__global__ void __launch_bounds__(256, 2)
gemm_tf32_mma(const float* __restrict__ A, const float* __restrict__ B,
              const float* __restrict__ bias, float* __restrict__ C,
              int M, int N, int K, int round_out)
{
    extern __shared__ float smem[];
    const uint32_t sbase = smem_u32(smem);

    const int tid  = threadIdx.x;
    const int lane = tid & 31;
    const int wid  = tid >> 5;
    const int warp_m = wid >> 2;
    const int warp_n = wid & 3;
    const int g  = lane >> 2;
    const int t  = lane & 3;

    const int bm = blockIdx.y * 128;
    const int bn = blockIdx.x * 128;
    const int NCH = K >> 5;

    float acc[4][4][4];
#pragma unroll
    for (int i = 0; i < 4; i++)
#pragma unroll
        for (int j = 0; j < 4; j++)
#pragma unroll
            for (int r = 0; r < 4; r++) acc[i][j][r] = 0.f;

    auto load_chunk = [&](int kc, int s) {
        const uint32_t sa = sbase + s * STAGE_BYTES;
        const float* ga = A + (size_t)bm * K + kc * 32;
        const float* gb = B + (size_t)bn * K + kc * 32;
#pragma unroll
        for (int j = 0; j < 4; j++) {
            int u = tid + 256 * j;
            int row = u >> 3, c = u & 7;
            uint32_t off = (row * ROWPAD + c * 4) * 4;
            cp_async16(sa + off,                   ga + (size_t)row * K + c * 4);
            cp_async16(sa + TILE_FLOATS * 4 + off, gb + (size_t)row * K + c * 4);
        }
        cp_commit();
    };

    auto compute = [&](int s) {
        const uint32_t* As = (const uint32_t*)(smem + s * STAGE_FLOATS);
        const uint32_t* Bs = As + TILE_FLOATS;
#pragma unroll
        for (int ks = 0; ks < 4; ks++) {
            const int k0 = ks * 8;
            uint32_t a[4][4], b[4][2];
#pragma unroll
            for (int mi = 0; mi < 4; mi++) {
                int row = warp_m * 64 + mi * 16;
                a[mi][0] = As[(row + g)     * ROWPAD + k0 + t];
                a[mi][1] = As[(row + g + 8) * ROWPAD + k0 + t];
                a[mi][2] = As[(row + g)     * ROWPAD + k0 + t + 4];
                a[mi][3] = As[(row + g + 8) * ROWPAD + k0 + t + 4];
            }
#pragma unroll
            for (int ni = 0; ni < 4; ni++) {
                int col = warp_n * 32 + ni * 8;
                b[ni][0] = Bs[(col + g) * ROWPAD + k0 + t];
                b[ni][1] = Bs[(col + g) * ROWPAD + k0 + t + 4];
            }
#pragma unroll
            for (int mi = 0; mi < 4; mi++)
#pragma unroll
                for (int ni = 0; ni < 4; ni++)
                    mma_tf32_16n8k8(acc[mi][ni], a[mi], b[ni]);
        }
    };

    load_chunk(0, 0);
    for (int kc = 0; kc < NCH; kc++) {
        const int s = kc & 1;
        if (kc + 1 < NCH) { load_chunk(kc + 1, s ^ 1); cp_wait<1>(); }
        else              { cp_wait<0>(); }
        __syncthreads();
        compute(s);
        __syncthreads();
    }

#pragma unroll
    for (int mi = 0; mi < 4; mi++) {
        const int row0 = bm + warp_m * 64 + mi * 16 + g;
#pragma unroll
        for (int ni = 0; ni < 4; ni++) {
            const int col = bn + warp_n * 32 + ni * 8 + t * 2;
            const float bx = bias[col], by = bias[col + 1];
            float2 v0 = make_float2(acc[mi][ni][0] + bx, acc[mi][ni][1] + by);
            float2 v1 = make_float2(acc[mi][ni][2] + bx, acc[mi][ni][3] + by);
            if (round_out) {
                v0.x = tf32_rn(v0.x); v0.y = tf32_rn(v0.y);
                v1.x = tf32_rn(v1.x); v1.y = tf32_rn(v1.y);
            }
            *(float2*)(C + (size_t)row0 * N + col)       = v0;
            *(float2*)(C + (size_t)(row0 + 8) * N + col) = v1;
        }
    }
}

// ---------------------------------------------------------------------------
// Flash causal attention with tf32 mma.sync products.
// One block = (64-row query tile, head); 256 threads = 8 warps in 4(m)x2(n).
// S = Q*K^T and O += P*V both via m16n8k8. Online softmax in SMEM.
// qkv values are tf32-pre-rounded by the QKV GEMM epilogue.
// ---------------------------------------------------------------------------
#define APAD 68   // floats per SMEM row (bank stride 4 -> conflict-free frags)

__global__ void __launch_bounds__(256) attn_mma_kernel(
    const float* __restrict__ qkv, float* __restrict__ ctx)
{
    extern __shared__ float sm[];
    float* Qs   = sm;                    // 64*APAD
    float* KVs  = sm + 64 * APAD;        // 64*APAD (K, then V)
    float* Ss   = sm + 2 * 64 * APAD;    // 64*APAD (S -> P)
    float* mst  = sm + 3 * 64 * APAD;
    float* lst  = mst + 64;
    float* corr = lst + 64;

    const int tid  = threadIdx.x;
    const int lane = tid & 31;
    const int wid  = tid >> 5;
    const int wm = wid >> 1;            // 0..3 : 16-row warp tile
    const int wn = wid & 1;             // 0..1 : 32-col warp tile
    const int g  = lane >> 2;
    const int t  = lane & 3;
    const int qi = 63 - blockIdx.x;     // heavy tiles first
    const int h  = blockIdx.y;
    const int hoff = h * DHEAD;

    const uint32_t sQ  = smem_u32(Qs);
    const uint32_t sKV = smem_u32(KVs);
    const uint32_t* Qu = (const uint32_t*)Qs;
    const uint32_t* Ku = (const uint32_t*)KVs;
    const uint32_t* Su = (const uint32_t*)Ss;

    // async loads: 64 rows x 64 floats = 1024 x 16B chunks, 4 per thread
    auto load_tile = [&](uint32_t sdst, int tile, int sect) {
#pragma unroll
        for (int j = 0; j < 4; j++) {
            int u = tid + 256 * j;
            int row = u >> 4, c = u & 15;
            cp_async16(sdst + row * (APAD * 4) + c * 16,
                       qkv + (size_t)(tile * 64 + row) * QKV_LD + sect + hoff + c * 4);
        }
        cp_commit();
    };

    load_tile(sQ, qi, 0);           // Q
    load_tile(sKV, 0, D_MODEL);     // K tile 0

    if (tid < 64) { mst[tid] = -1e30f; lst[tid] = 0.f; }

    float oacc[4][4];
#pragma unroll
    for (int i = 0; i < 4; i++)
#pragma unroll
        for (int r = 0; r < 4; r++) oacc[i][r] = 0.f;

    const int r0 = wm * 16 + g;     // local rows owned by this thread
    const int r1 = r0 + 8;

    cp_wait<0>();
    __syncthreads();                // Q + K0 ready

    for (int jt = 0; jt <= qi; jt++) {
        // ---- S = Q * K^T (tf32 mma), scale folded after
        float sacc[4][4];
#pragma unroll
        for (int i = 0; i < 4; i++)
#pragma unroll
            for (int r = 0; r < 4; r++) sacc[i][r] = 0.f;
#pragma unroll
        for (int ks = 0; ks < 8; ks++) {
            const int k0 = ks * 8;
            uint32_t a[4], b[4][2];
            a[0] = Qu[r0 * APAD + k0 + t];
            a[1] = Qu[r1 * APAD + k0 + t];
            a[2] = Qu[r0 * APAD + k0 + t + 4];
            a[3] = Qu[r1 * APAD + k0 + t + 4];
#pragma unroll
            for (int ni = 0; ni < 4; ni++) {
                int col = wn * 32 + ni * 8;
                b[ni][0] = Ku[(col + g) * APAD + k0 + t];
                b[ni][1] = Ku[(col + g) * APAD + k0 + t + 4];
            }
#pragma unroll
            for (int ni = 0; ni < 4; ni++)
                mma_tf32_16n8k8(sacc[ni], a, b[ni]);
        }
        const bool diag = (jt == qi);
#pragma unroll
        for (int ni = 0; ni < 4; ni++) {
            const int col = wn * 32 + ni * 8 + t * 2;
            float v0 = sacc[ni][0] * 0.125f, v1 = sacc[ni][1] * 0.125f;
            float v2 = sacc[ni][2] * 0.125f, v3 = sacc[ni][3] * 0.125f;
            if (diag) {
                if (col     > r0) v0 = -1e30f;
                if (col + 1 > r0) v1 = -1e30f;
                if (col     > r1) v2 = -1e30f;
                if (col + 1 > r1) v3 = -1e30f;
            }
            *(float2*)(Ss + r0 * APAD + col) = make_float2(v0, v1);
            *(float2*)(Ss + r1 * APAD + col) = make_float2(v2, v3);
        }
        __syncthreads();            // S complete; KVs free

        // V tile load overlaps softmax
        load_tile(sKV, jt, 2 * D_MODEL);

        // ---- online softmax: 4 threads/row, 16 contiguous cols each
        {
            const int row = tid >> 2;
            const int l4  = tid & 3;
            const int cb  = l4 * 16;
            float tmax = -1e30f;
#pragma unroll
            for (int c = 0; c < 16; c++)
                tmax = fmaxf(tmax, Ss[row * APAD + cb + c]);
            tmax = fmaxf(tmax, __shfl_xor_sync(0xffffffffu, tmax, 1));
            tmax = fmaxf(tmax, __shfl_xor_sync(0xffffffffu, tmax, 2));
            const float mold = mst[row];
            const float mnew = fmaxf(mold, tmax);
            float lsum = 0.f;
#pragma unroll
            for (int c = 0; c < 16; c++) {
                float p = __expf(Ss[row * APAD + cb + c] - mnew);
                Ss[row * APAD + cb + c] = tf32_rn(p);
                lsum += p;
            }
            lsum += __shfl_xor_sync(0xffffffffu, lsum, 1);
            lsum += __shfl_xor_sync(0xffffffffu, lsum, 2);
            if (l4 == 0) {
                const float cr = __expf(mold - mnew);
                mst[row]  = mnew;
                lst[row]  = lst[row] * cr + lsum;
                corr[row] = cr;
            }
        }
        cp_wait<0>();
        __syncthreads();            // P + state + V ready

        // ---- rescale O, then O += P * V (tf32 mma)
        {
            const float cr0 = corr[r0], cr1 = corr[r1];
#pragma unroll
            for (int ni = 0; ni < 4; ni++) {
                oacc[ni][0] *= cr0; oacc[ni][1] *= cr0;
                oacc[ni][2] *= cr1; oacc[ni][3] *= cr1;
            }
        }
#pragma unroll
        for (int ks = 0; ks < 8; ks++) {
            const int k0 = ks * 8;
            uint32_t a[4], b[4][2];
            a[0] = Su[r0 * APAD + k0 + t];
            a[1] = Su[r1 * APAD + k0 + t];
            a[2] = Su[r0 * APAD + k0 + t + 4];
            a[3] = Su[r1 * APAD + k0 + t + 4];
#pragma unroll
            for (int ni = 0; ni < 4; ni++) {
                int col = wn * 32 + ni * 8;
                b[ni][0] = Ku[(k0 + t)     * APAD + col + g];   // V[n][d]
                b[ni][1] = Ku[(k0 + t + 4) * APAD + col + g];
            }
#pragma unroll
            for (int ni = 0; ni < 4; ni++)
                mma_tf32_16n8k8(oacc[ni], a, b[ni]);
        }
        __syncthreads();            // PV done; KVs free for next K

        if (jt < qi) {
            load_tile(sKV, jt + 1, D_MODEL);
            cp_wait<0>();
            __syncthreads();
        }
    }

    // ---- normalize and write context (tf32-rounded for the out-proj GEMM)
    {
        const float inv0 = 1.f / lst[r0];
        const float inv1 = 1.f / lst[r1];
#pragma unroll
        for (int ni = 0; ni < 4; ni++) {
            const int col = hoff + wn * 32 + ni * 8 + t * 2;
            float* c0 = ctx + (size_t)(qi * 64 + r0) * D_MODEL + col;
            float* c1 = ctx + (size_t)(qi * 64 + r1) * D_MODEL + col;
            c0[0] = tf32_rn(oacc[ni][0] * inv0);
            c0[1] = tf32_rn(oacc[ni][1] * inv0);
            c1[0] = tf32_rn(oacc[ni][2] * inv1);
            c1[1] = tf32_rn(oacc[ni][3] * inv1);
        }
    }
}

// ---------------------------------------------------------------------------
extern "C" void kernel_launch(void* const* d_in, const int* in_sizes, int n_in,
                              void* d_out, int out_size)
{
    const float* x      = (const float*)d_in[0];
    const float* Wqkv_w = (const float*)d_in[1];
    const float* Wqkv_b = (const float*)d_in[2];
    const float* out_w  = (const float*)d_in[3];
    const float* out_b  = (const float*)d_in[4];
    float* out = (float*)d_out;

    float *qkv, *ctx, *xr, *wqkvr, *outwr;
    cudaGetSymbolAddress((void**)&qkv,   g_qkv);
    cudaGetSymbolAddress((void**)&ctx,   g_ctx);
    cudaGetSymbolAddress((void**)&xr,    g_xr);
    cudaGetSymbolAddress((void**)&wqkvr, g_wqkvr);
    cudaGetSymbolAddress((void**)&outwr, g_outwr);

    const int gemm_smem = 2 * STAGE_BYTES;   // 73728
    cudaFuncSetAttribute(gemm_tf32_mma,
                         cudaFuncAttributeMaxDynamicSharedMemorySize, gemm_smem);
    const int attn_smem = (3 * 64 * APAD + 3 * 64) * (int)sizeof(float); // 52992
    cudaFuncSetAttribute(attn_mma_kernel,
                         cudaFuncAttributeMaxDynamicSharedMemorySize, attn_smem);

    // 0) tf32-round tensor-core inputs
    {
        int n4 = S_LEN * D_MODEL / 4;
        round_tf32_kernel<<<(n4 + 255) / 256, 256>>>((const float4*)x,
                                                     (float4*)xr, n4);
        n4 = QKV_LD * D_MODEL / 4;
        round_tf32_kernel<<<(n4 + 255) / 256, 256>>>((const float4*)Wqkv_w,
                                                     (float4*)wqkvr, n4);
        n4 = D_MODEL * D_MODEL / 4;
        round_tf32_kernel<<<(n4 + 255) / 256, 256>>>((const float4*)out_w,
                                                     (float4*)outwr, n4);
    }

    // 1) QKV projection (outputs tf32-rounded for the attention mma)
    gemm_tf32_mma<<<dim3(QKV_LD / 128, S_LEN / 128), 256, gemm_smem>>>(
        xr, wqkvr, Wqkv_b, qkv, S_LEN, QKV_LD, D_MODEL, 1);

    // 2) Causal flash attention on tensor cores
    attn_mma_kernel<<<dim3(S_LEN / 64, NHEAD), 256, attn_smem>>>(qkv, ctx);

    // 3) Output projection (fp32 outputs)
    gemm_tf32_mma<<<dim3(D_MODEL / 128, S_LEN / 128), 256, gemm_smem>>>(
        ctx, outwr, out_b, out, S_LEN, D_MODEL, D_MODEL, 0);
}